// round 3
// baseline (speedup 1.0000x reference)
#include <cuda_runtime.h>
#include <math.h>

// Problem dims
#define B_ 1024
#define L_ 1024
#define T_ 32
#define H_ 2048
#define K_ 64
#define O_ 256

// Scratch (static device globals: allocation-guard safe)
__device__ float g_hidden[(size_t)T_ * B_ * H_];   // 256 MB, layout [t][b][h]
__device__ float g_sparse[(size_t)T_ * B_ * K_];   // 8 MB,   layout [t][b][k]

// ---------------------------------------------------------------------------
// Kernel 1: per-token GEMM  hidden[t] = x @ Wt[t]
//   A = x [1024 x 1024] row-major, B = Wt[t] [1024 x 2048] row-major
//   128x128 tile, BK=16, 256 threads, 8x8 micro-tile (fp32 FFMA)
// ---------------------------------------------------------------------------
#define BM 128
#define BN 128
#define BKK 16
#define TM 8
#define TN 8

__global__ __launch_bounds__(256) void gemm1_kernel(const float* __restrict__ x,
                                                    const float* __restrict__ Wt) {
    __shared__ float As[BKK][BM + 4];
    __shared__ float Bs[BKK][BN + 4];

    const int t  = blockIdx.z;
    const int m0 = blockIdx.y * BM;
    const int n0 = blockIdx.x * BN;

    const float* A    = x;
    const float* Bmat = Wt + (size_t)t * L_ * H_;
    float*       C    = g_hidden + (size_t)t * B_ * H_;

    const int tid = threadIdx.x;
    const int tx  = tid & 15;      // 0..15 (n)
    const int ty  = tid >> 4;      // 0..15 (m)

    float acc[TM][TN];
    #pragma unroll
    for (int i = 0; i < TM; i++)
        #pragma unroll
        for (int j = 0; j < TN; j++) acc[i][j] = 0.0f;

    for (int k0 = 0; k0 < L_; k0 += BKK) {
        // Load A tile 128x16 (transposed into As[k][m]); 512 float4 / 256 thr
        #pragma unroll
        for (int i = 0; i < 2; i++) {
            int idx = tid + i * 256;
            int c4  = idx & 3;          // k-group
            int row = idx >> 2;         // m
            float4 v = *(const float4*)(A + (size_t)(m0 + row) * L_ + k0 + c4 * 4);
            As[c4 * 4 + 0][row] = v.x;
            As[c4 * 4 + 1][row] = v.y;
            As[c4 * 4 + 2][row] = v.z;
            As[c4 * 4 + 3][row] = v.w;
        }
        // Load B tile 16x128 into Bs[k][n]; 512 float4 / 256 thr
        #pragma unroll
        for (int i = 0; i < 2; i++) {
            int idx = tid + i * 256;
            int c4  = idx & 31;         // n-group
            int r   = idx >> 5;         // k
            float4 v = *(const float4*)(Bmat + (size_t)(k0 + r) * H_ + n0 + c4 * 4);
            *(float4*)&Bs[r][c4 * 4] = v;   // (BN+4)*4 = 528B row stride, 16B aligned
        }
        __syncthreads();

        #pragma unroll
        for (int kk = 0; kk < BKK; kk++) {
            float a[TM], b[TN];
            #pragma unroll
            for (int i = 0; i < TM; i++) a[i] = As[kk][ty * TM + i];
            #pragma unroll
            for (int j = 0; j < TN; j++) b[j] = Bs[kk][tx * TN + j];
            #pragma unroll
            for (int i = 0; i < TM; i++)
                #pragma unroll
                for (int j = 0; j < TN; j++)
                    acc[i][j] += a[i] * b[j];
        }
        __syncthreads();
    }

    #pragma unroll
    for (int i = 0; i < TM; i++) {
        int m = m0 + ty * TM + i;
        #pragma unroll
        for (int j = 0; j < TN; j += 4) {
            float4 v = make_float4(acc[i][j], acc[i][j + 1], acc[i][j + 2], acc[i][j + 3]);
            *(float4*)(C + (size_t)m * H_ + n0 + tx * TN + j) = v;
        }
    }
}

// ---------------------------------------------------------------------------
// Kernel 2: top-64 (sorted descending) per (b,t) row of 2048 via bitonic sort
// ---------------------------------------------------------------------------
__global__ __launch_bounds__(256) void topk_kernel() {
    __shared__ float s[H_];
    const int b = blockIdx.x;
    const int t = blockIdx.y;
    const float* row = g_hidden + ((size_t)t * B_ + b) * H_;

    #pragma unroll
    for (int i = threadIdx.x; i < H_; i += 256) s[i] = row[i];
    __syncthreads();

    for (int k = 2; k <= H_; k <<= 1) {
        for (int j = k >> 1; j > 0; j >>= 1) {
            #pragma unroll
            for (int i = threadIdx.x; i < H_; i += 256) {
                int ixj = i ^ j;
                if (ixj > i) {
                    float a  = s[i];
                    float bb = s[ixj];
                    bool desc = ((i & k) == 0);
                    if (desc ? (a < bb) : (a > bb)) { s[i] = bb; s[ixj] = a; }
                }
            }
            __syncthreads();
        }
    }
    if (threadIdx.x < K_)
        g_sparse[((size_t)t * B_ + b) * K_ + threadIdx.x] = s[threadIdx.x];
}

// ---------------------------------------------------------------------------
// Kernel 3: y = g @ dense_W[t] + b -> exact GELU -> LayerNorm(O) * gamma + beta
//   One block per (b,t); 256 threads, one output each. dense_W (2 MB) is
//   L2-resident so the K loop streams from L2.
// ---------------------------------------------------------------------------
__global__ __launch_bounds__(256) void dense_kernel(const float* __restrict__ dW,
                                                    const float* __restrict__ db,
                                                    const float* __restrict__ gamma,
                                                    const float* __restrict__ beta,
                                                    float* __restrict__ out) {
    __shared__ float gs[K_];
    __shared__ float red[8];
    __shared__ float s_mean, s_rstd;

    const int b = blockIdx.x;
    const int t = blockIdx.y;
    const int o = threadIdx.x;

    if (o < K_) gs[o] = g_sparse[((size_t)t * B_ + b) * K_ + o];
    __syncthreads();

    const float* W = dW + (size_t)t * K_ * O_;
    float acc = db[t * O_ + o];
    #pragma unroll
    for (int k = 0; k < K_; k++)
        acc = fmaf(gs[k], W[k * O_ + o], acc);

    // exact GELU: 0.5*x*(1+erf(x/sqrt(2)))
    float y = 0.5f * acc * (1.0f + erff(acc * 0.70710678118654752f));

    // mean over 256
    float v = y;
    #pragma unroll
    for (int off = 16; off; off >>= 1) v += __shfl_xor_sync(0xffffffffu, v, off);
    if ((o & 31) == 0) red[o >> 5] = v;
    __syncthreads();
    if (o < 8) {
        float w = red[o];
        #pragma unroll
        for (int off = 4; off; off >>= 1) w += __shfl_xor_sync(0xffu, w, off);
        if (o == 0) s_mean = w * (1.0f / O_);
    }
    __syncthreads();

    // variance over 256 (two-pass, matches reference exactly)
    float d = y - s_mean;
    v = d * d;
    #pragma unroll
    for (int off = 16; off; off >>= 1) v += __shfl_xor_sync(0xffffffffu, v, off);
    if ((o & 31) == 0) red[o >> 5] = v;
    __syncthreads();
    if (o < 8) {
        float w = red[o];
        #pragma unroll
        for (int off = 4; off; off >>= 1) w += __shfl_xor_sync(0xffu, w, off);
        if (o == 0) s_rstd = rsqrtf(w * (1.0f / O_) + 1e-6f);
    }
    __syncthreads();

    out[((size_t)b * T_ + t) * O_ + o] =
        d * s_rstd * gamma[t * O_ + o] + beta[t * O_ + o];
}

// ---------------------------------------------------------------------------
extern "C" void kernel_launch(void* const* d_in, const int* in_sizes, int n_in,
                              void* d_out, int out_size) {
    const float* x     = (const float*)d_in[0];   // [1024,1024]
    const float* Wt    = (const float*)d_in[1];   // [32,1024,2048]
    const float* dW    = (const float*)d_in[2];   // [32,64,256]
    const float* db    = (const float*)d_in[3];   // [32,256]
    const float* gamma = (const float*)d_in[4];   // [32,256]
    const float* beta  = (const float*)d_in[5];   // [32,256]
    float* out = (float*)d_out;                   // [1024,32,256]

    dim3 g1(H_ / BN, B_ / BM, T_);
    gemm1_kernel<<<g1, 256>>>(x, Wt);
    topk_kernel<<<dim3(B_, T_), 256>>>();
    dense_kernel<<<dim3(B_, T_), 256>>>(dW, db, gamma, beta, out);
}

// round 7
// speedup vs baseline: 1.3976x; 1.3976x over previous
#include <cuda_runtime.h>
#include <cuda_bf16.h>
#include <math.h>
#include <stdint.h>

#define B_ 1024
#define L_ 1024
#define T_ 32
#define H_ 2048
#define K_ 64
#define O_ 256

// ---------------- static device scratch (allocation-guard safe) ------------
__device__ float g_hidden[(size_t)T_ * B_ * H_];          // 256 MB [t][b][h]
__device__ float g_sparse[(size_t)T_ * B_ * K_];          // 8 MB
__device__ __nv_bfloat16 g_xh[(size_t)B_ * L_];           // [b][l] hi
__device__ __nv_bfloat16 g_xl[(size_t)B_ * L_];           // [b][l] lo
__device__ __nv_bfloat16 g_wh[(size_t)T_ * L_ * H_];      // [t][l][h] hi (k-major)
__device__ __nv_bfloat16 g_wl[(size_t)T_ * L_ * H_];      // [t][l][h] lo

// ---------------- helpers ---------------------------------------------------
__device__ __forceinline__ uint32_t smem_u32(const void* p) {
    uint32_t a;
    asm("{ .reg .u64 t; cvta.to.shared.u64 t, %1; cvt.u32.u64 %0, t; }"
        : "=r"(a) : "l"(p));
    return a;
}
__device__ __forceinline__ void cpa16(uint32_t s, const void* g) {
    asm volatile("cp.async.cg.shared.global [%0], [%1], 16;" :: "r"(s), "l"(g));
}
#define CPA_COMMIT() asm volatile("cp.async.commit_group;" ::: "memory")
#define CPA_WAIT(n)  asm volatile("cp.async.wait_group %0;" :: "n"(n) : "memory")

#define LDSM4(r0, r1, r2, r3, a)                                               \
    asm volatile("ldmatrix.sync.aligned.m8n8.x4.shared.b16 {%0,%1,%2,%3},[%4];"\
                 : "=r"(r0), "=r"(r1), "=r"(r2), "=r"(r3) : "r"(a))
#define LDSM4T(r0, r1, r2, r3, a)                                              \
    asm volatile("ldmatrix.sync.aligned.m8n8.x4.trans.shared.b16 "             \
                 "{%0,%1,%2,%3},[%4];"                                         \
                 : "=r"(r0), "=r"(r1), "=r"(r2), "=r"(r3) : "r"(a))
#define MMA16816(c, a0, a1, a2, a3, b0, b1)                                    \
    asm volatile("mma.sync.aligned.m16n8k16.row.col.f32.bf16.bf16.f32 "        \
                 "{%0,%1,%2,%3},{%4,%5,%6,%7},{%8,%9},{%0,%1,%2,%3};"          \
                 : "+f"((c)[0]), "+f"((c)[1]), "+f"((c)[2]), "+f"((c)[3])      \
                 : "r"(a0), "r"(a1), "r"(a2), "r"(a3), "r"(b0), "r"(b1))

// ---------------- conversion: f32 -> (hi, lo) bf16 --------------------------
__global__ __launch_bounds__(256) void conv_split(const float* __restrict__ src,
                                                  __nv_bfloat16* __restrict__ dh,
                                                  __nv_bfloat16* __restrict__ dl) {
    size_t i = (size_t)blockIdx.x * 256 + threadIdx.x;   // float4 index
    float4 v = ((const float4*)src)[i];
    float vv[4] = {v.x, v.y, v.z, v.w};
    __nv_bfloat16 hi[4], lo[4];
    #pragma unroll
    for (int j = 0; j < 4; j++) {
        hi[j] = __float2bfloat16(vv[j]);
        lo[j] = __float2bfloat16(vv[j] - __bfloat162float(hi[j]));
    }
    ((uint2*)dh)[i] = *(uint2*)hi;
    ((uint2*)dl)[i] = *(uint2*)lo;
}

// ---------------- HMMA GEMM: hidden[t] = x @ Wt[t] --------------------------
// block tile 128m x 128n, BK=32; 8 warps, warp tile 32m x 64n; split-bf16 3-MMA
#define BM 128
#define BN 128
#define BKC 32
#define NCH (L_ / BKC)          // 32 chunks

// smem (halves): padded rows, conflict-free for ldmatrix
#define A_STRIDE 40             // 128 rows * 40  (80 B/row)
#define B_STRIDE 136            // 32 rows * 136  (272 B/row)
#define AH_OFF 0
#define AL_OFF (128 * A_STRIDE)                  // 5120
#define BH_OFF (2 * 128 * A_STRIDE)              // 10240
#define BL_OFF (BH_OFF + 32 * B_STRIDE)          // 14592
#define STAGE_H (BL_OFF + 32 * B_STRIDE)         // 18944 halves = 37888 B
#define GEMM_SMEM (2 * STAGE_H * 2)              // 75776 B

__global__ __launch_bounds__(256) void gemm_mma() {
    extern __shared__ __align__(16) __nv_bfloat16 sm[];
    const uint32_t sbase = smem_u32(sm);
    const int tid  = threadIdx.x;
    const int wid  = tid >> 5;
    const int lane = tid & 31;
    const int t  = blockIdx.z;
    const int m0 = blockIdx.x * BM;
    const int n0 = blockIdx.y * BN;
    const int wm = (wid & 3) * 32;      // warp m offset in tile
    const int wn = (wid >> 2) * 64;     // warp n offset in tile

    const __nv_bfloat16* Wh = g_wh + (size_t)t * L_ * H_;
    const __nv_bfloat16* Wl = g_wl + (size_t)t * L_ * H_;

    // per-thread prefetch coordinates
    const int a_row0 = tid >> 2, a_kc = (tid & 3) * 8;           // +256 -> +64 rows
    const int b_kr0  = tid >> 4, b_nc = (tid & 15) * 8;          // +256 -> +16 k rows

    auto prefetch = [&](int c) {
        const int k0 = c * BKC;
        const uint32_t st = sbase + (uint32_t)((c & 1) * STAGE_H) * 2;
        #pragma unroll
        for (int i = 0; i < 2; i++) {
            int row = a_row0 + i * 64;
            size_t g = (size_t)(m0 + row) * L_ + k0 + a_kc;
            uint32_t so = (uint32_t)(row * A_STRIDE + a_kc) * 2;
            cpa16(st + AH_OFF * 2 + so, g_xh + g);
            cpa16(st + AL_OFF * 2 + so, g_xl + g);
        }
        #pragma unroll
        for (int i = 0; i < 2; i++) {
            int kr = b_kr0 + i * 16;
            size_t g = (size_t)(k0 + kr) * H_ + n0 + b_nc;
            uint32_t so = (uint32_t)(kr * B_STRIDE + b_nc) * 2;
            cpa16(st + BH_OFF * 2 + so, Wh + g);
            cpa16(st + BL_OFF * 2 + so, Wl + g);
        }
    };

    float acc[2][8][4];
    #pragma unroll
    for (int mi = 0; mi < 2; mi++)
        #pragma unroll
        for (int ni = 0; ni < 8; ni++)
            #pragma unroll
            for (int j = 0; j < 4; j++) acc[mi][ni][j] = 0.0f;

    prefetch(0); CPA_COMMIT();

    // ldmatrix per-lane address pieces
    const int a_lm_row = wm + (lane & 15);            // + mi*16
    const int a_lm_col = (lane >> 4) * 8;             // + ks*16
    const int b_lm_row = (lane < 16) ? lane : (lane - 16);   // + ks*16
    const int b_lm_col = wn + ((lane >> 4) * 8);      // + nb*16

    for (int c = 0; c < NCH; c++) {
        if (c + 1 < NCH) { prefetch(c + 1); CPA_COMMIT(); CPA_WAIT(1); }
        else             { CPA_WAIT(0); }
        __syncthreads();

        const uint32_t st = sbase + (uint32_t)((c & 1) * STAGE_H) * 2;
        #pragma unroll
        for (int ks = 0; ks < 2; ks++) {
            uint32_t a[2][4], b[4][4];
            // ---- pass 0: Ah x Bh ----
            #pragma unroll
            for (int mi = 0; mi < 2; mi++) {
                uint32_t ad = st + AH_OFF * 2 +
                    (uint32_t)((a_lm_row + mi * 16) * A_STRIDE + a_lm_col + ks * 16) * 2;
                LDSM4(a[mi][0], a[mi][1], a[mi][2], a[mi][3], ad);
            }
            #pragma unroll
            for (int nb = 0; nb < 4; nb++) {
                uint32_t bd = st + BH_OFF * 2 +
                    (uint32_t)((b_lm_row + ks * 16) * B_STRIDE + b_lm_col + nb * 16) * 2;
                LDSM4T(b[nb][0], b[nb][1], b[nb][2], b[nb][3], bd);
            }
            #pragma unroll
            for (int mi = 0; mi < 2; mi++)
                #pragma unroll
                for (int ni = 0; ni < 8; ni++)
                    MMA16816(acc[mi][ni], a[mi][0], a[mi][1], a[mi][2], a[mi][3],
                             b[ni >> 1][(ni & 1) * 2], b[ni >> 1][(ni & 1) * 2 + 1]);
            // ---- pass 1: Ah x Bl ----
            #pragma unroll
            for (int nb = 0; nb < 4; nb++) {
                uint32_t bd = st + BL_OFF * 2 +
                    (uint32_t)((b_lm_row + ks * 16) * B_STRIDE + b_lm_col + nb * 16) * 2;
                LDSM4T(b[nb][0], b[nb][1], b[nb][2], b[nb][3], bd);
            }
            #pragma unroll
            for (int mi = 0; mi < 2; mi++)
                #pragma unroll
                for (int ni = 0; ni < 8; ni++)
                    MMA16816(acc[mi][ni], a[mi][0], a[mi][1], a[mi][2], a[mi][3],
                             b[ni >> 1][(ni & 1) * 2], b[ni >> 1][(ni & 1) * 2 + 1]);
            // ---- pass 2: Al x Bh ----
            #pragma unroll
            for (int mi = 0; mi < 2; mi++) {
                uint32_t ad = st + AL_OFF * 2 +
                    (uint32_t)((a_lm_row + mi * 16) * A_STRIDE + a_lm_col + ks * 16) * 2;
                LDSM4(a[mi][0], a[mi][1], a[mi][2], a[mi][3], ad);
            }
            #pragma unroll
            for (int nb = 0; nb < 4; nb++) {
                uint32_t bd = st + BH_OFF * 2 +
                    (uint32_t)((b_lm_row + ks * 16) * B_STRIDE + b_lm_col + nb * 16) * 2;
                LDSM4T(b[nb][0], b[nb][1], b[nb][2], b[nb][3], bd);
            }
            #pragma unroll
            for (int mi = 0; mi < 2; mi++)
                #pragma unroll
                for (int ni = 0; ni < 8; ni++)
                    MMA16816(acc[mi][ni], a[mi][0], a[mi][1], a[mi][2], a[mi][3],
                             b[ni >> 1][(ni & 1) * 2], b[ni >> 1][(ni & 1) * 2 + 1]);
        }
        __syncthreads();
    }

    // epilogue: direct fp32 store to g_hidden
    float* C = g_hidden + (size_t)t * B_ * H_;
    #pragma unroll
    for (int mi = 0; mi < 2; mi++) {
        int row = m0 + wm + mi * 16 + (lane >> 2);
        #pragma unroll
        for (int ni = 0; ni < 8; ni++) {
            int col = n0 + wn + ni * 8 + (lane & 3) * 2;
            *(float2*)(C + (size_t)row * H_ + col) =
                make_float2(acc[mi][ni][0], acc[mi][ni][1]);
            *(float2*)(C + (size_t)(row + 8) * H_ + col) =
                make_float2(acc[mi][ni][2], acc[mi][ni][3]);
        }
    }
}

// ---------------- top-64 per (b,t) via bitonic sort -------------------------
__global__ __launch_bounds__(256) void topk_kernel() {
    __shared__ float s[H_];
    const int b = blockIdx.x;
    const int t = blockIdx.y;
    const float* row = g_hidden + ((size_t)t * B_ + b) * H_;
    for (int i = threadIdx.x; i < H_; i += 256) s[i] = row[i];
    __syncthreads();
    for (int k = 2; k <= H_; k <<= 1) {
        for (int j = k >> 1; j > 0; j >>= 1) {
            for (int i = threadIdx.x; i < H_; i += 256) {
                int ixj = i ^ j;
                if (ixj > i) {
                    float a = s[i], bb = s[ixj];
                    bool desc = ((i & k) == 0);
                    if (desc ? (a < bb) : (a > bb)) { s[i] = bb; s[ixj] = a; }
                }
            }
            __syncthreads();
        }
    }
    if (threadIdx.x < K_)
        g_sparse[((size_t)t * B_ + b) * K_ + threadIdx.x] = s[threadIdx.x];
}

// ---------------- dense + GELU + LayerNorm ----------------------------------
__global__ __launch_bounds__(256) void dense_kernel(const float* __restrict__ dW,
                                                    const float* __restrict__ db,
                                                    const float* __restrict__ gamma,
                                                    const float* __restrict__ beta,
                                                    float* __restrict__ out) {
    __shared__ float gs[K_];
    __shared__ float red[8];
    __shared__ float s_mean, s_rstd;
    const int b = blockIdx.x;
    const int t = blockIdx.y;
    const int o = threadIdx.x;

    if (o < K_) gs[o] = g_sparse[((size_t)t * B_ + b) * K_ + o];
    __syncthreads();

    const float* W = dW + (size_t)t * K_ * O_;
    float acc = db[t * O_ + o];
    #pragma unroll
    for (int k = 0; k < K_; k++) acc = fmaf(gs[k], W[k * O_ + o], acc);

    float y = 0.5f * acc * (1.0f + erff(acc * 0.70710678118654752f));

    float v = y;
    #pragma unroll
    for (int off = 16; off; off >>= 1) v += __shfl_xor_sync(0xffffffffu, v, off);
    if ((o & 31) == 0) red[o >> 5] = v;
    __syncthreads();
    if (o < 8) {
        float w = red[o];
        #pragma unroll
        for (int off = 4; off; off >>= 1) w += __shfl_xor_sync(0xffu, w, off);
        if (o == 0) s_mean = w * (1.0f / O_);
    }
    __syncthreads();
    float d = y - s_mean;
    v = d * d;
    #pragma unroll
    for (int off = 16; off; off >>= 1) v += __shfl_xor_sync(0xffffffffu, v, off);
    if ((o & 31) == 0) red[o >> 5] = v;
    __syncthreads();
    if (o < 8) {
        float w = red[o];
        #pragma unroll
        for (int off = 4; off; off >>= 1) w += __shfl_xor_sync(0xffu, w, off);
        if (o == 0) s_rstd = rsqrtf(w * (1.0f / O_) + 1e-6f);
    }
    __syncthreads();

    out[((size_t)b * T_ + t) * O_ + o] =
        d * s_rstd * gamma[t * O_ + o] + beta[t * O_ + o];
}

// ---------------------------------------------------------------------------
extern "C" void kernel_launch(void* const* d_in, const int* in_sizes, int n_in,
                              void* d_out, int out_size) {
    const float* x     = (const float*)d_in[0];
    const float* Wt    = (const float*)d_in[1];
    const float* dW    = (const float*)d_in[2];
    const float* db    = (const float*)d_in[3];
    const float* gamma = (const float*)d_in[4];
    const float* beta  = (const float*)d_in[5];
    float* out = (float*)d_out;

    __nv_bfloat16 *xh, *xl, *wh, *wl;
    cudaGetSymbolAddress((void**)&xh, g_xh);
    cudaGetSymbolAddress((void**)&xl, g_xl);
    cudaGetSymbolAddress((void**)&wh, g_wh);
    cudaGetSymbolAddress((void**)&wl, g_wl);

    cudaFuncSetAttribute(gemm_mma, cudaFuncAttributeMaxDynamicSharedMemorySize,
                         GEMM_SMEM);

    conv_split<<<(B_ * L_ / 4) / 256, 256>>>(x, xh, xl);
    conv_split<<<((size_t)T_ * L_ * H_ / 4) / 256, 256>>>(Wt, wh, wl);
    gemm_mma<<<dim3(B_ / BM, H_ / BN, T_), 256, GEMM_SMEM>>>();
    topk_kernel<<<dim3(B_, T_), 256>>>();
    dense_kernel<<<dim3(B_, T_), 256>>>(dW, db, gamma, beta, out);
}

// round 9
// speedup vs baseline: 3.4959x; 2.5014x over previous
#include <cuda_runtime.h>
#include <cuda_bf16.h>
#include <math.h>
#include <stdint.h>

#define B_ 1024
#define L_ 1024
#define T_ 32
#define H_ 2048
#define K_ 64
#define O_ 256

// ---------------- static device scratch (allocation-guard safe) ------------
__device__ float g_hidden[(size_t)T_ * B_ * H_];          // 256 MB [t][b][h]
__device__ float g_sparse[(size_t)T_ * B_ * K_];          // 8 MB
__device__ __nv_bfloat16 g_xh[(size_t)B_ * L_];           // [b][l] hi
__device__ __nv_bfloat16 g_xl[(size_t)B_ * L_];           // [b][l] lo
__device__ __nv_bfloat16 g_wh[(size_t)T_ * L_ * H_];      // [t][l][h] hi (k-major)
__device__ __nv_bfloat16 g_wl[(size_t)T_ * L_ * H_];      // [t][l][h] lo

// ---------------- helpers ---------------------------------------------------
__device__ __forceinline__ uint32_t smem_u32(const void* p) {
    uint32_t a;
    asm("{ .reg .u64 t; cvta.to.shared.u64 t, %1; cvt.u32.u64 %0, t; }"
        : "=r"(a) : "l"(p));
    return a;
}
__device__ __forceinline__ void cpa16(uint32_t s, const void* g) {
    asm volatile("cp.async.cg.shared.global [%0], [%1], 16;" :: "r"(s), "l"(g));
}
#define CPA_COMMIT() asm volatile("cp.async.commit_group;" ::: "memory")
#define CPA_WAIT(n)  asm volatile("cp.async.wait_group %0;" :: "n"(n) : "memory")

#define LDSM4(r0, r1, r2, r3, a)                                               \
    asm volatile("ldmatrix.sync.aligned.m8n8.x4.shared.b16 {%0,%1,%2,%3},[%4];"\
                 : "=r"(r0), "=r"(r1), "=r"(r2), "=r"(r3) : "r"(a))
#define LDSM4T(r0, r1, r2, r3, a)                                              \
    asm volatile("ldmatrix.sync.aligned.m8n8.x4.trans.shared.b16 "             \
                 "{%0,%1,%2,%3},[%4];"                                         \
                 : "=r"(r0), "=r"(r1), "=r"(r2), "=r"(r3) : "r"(a))
#define MMA16816(c, a0, a1, a2, a3, b0, b1)                                    \
    asm volatile("mma.sync.aligned.m16n8k16.row.col.f32.bf16.bf16.f32 "        \
                 "{%0,%1,%2,%3},{%4,%5,%6,%7},{%8,%9},{%0,%1,%2,%3};"          \
                 : "+f"((c)[0]), "+f"((c)[1]), "+f"((c)[2]), "+f"((c)[3])      \
                 : "r"(a0), "r"(a1), "r"(a2), "r"(a3), "r"(b0), "r"(b1))

// ---------------- conversion: f32 -> (hi, lo) bf16 --------------------------
__global__ __launch_bounds__(256) void conv_split(const float* __restrict__ src,
                                                  __nv_bfloat16* __restrict__ dh,
                                                  __nv_bfloat16* __restrict__ dl) {
    size_t i = (size_t)blockIdx.x * 256 + threadIdx.x;   // float4 index
    float4 v = ((const float4*)src)[i];
    float vv[4] = {v.x, v.y, v.z, v.w};
    __nv_bfloat16 hi[4], lo[4];
    #pragma unroll
    for (int j = 0; j < 4; j++) {
        hi[j] = __float2bfloat16(vv[j]);
        lo[j] = __float2bfloat16(vv[j] - __bfloat162float(hi[j]));
    }
    ((uint2*)dh)[i] = *(uint2*)hi;
    ((uint2*)dl)[i] = *(uint2*)lo;
}

// ---------------- HMMA GEMM: hidden[t] = x @ Wt[t] --------------------------
#define BM 128
#define BN 128
#define BKC 32
#define NCH (L_ / BKC)          // 32 chunks

#define A_STRIDE 40
#define B_STRIDE 136
#define AH_OFF 0
#define AL_OFF (128 * A_STRIDE)
#define BH_OFF (2 * 128 * A_STRIDE)
#define BL_OFF (BH_OFF + 32 * B_STRIDE)
#define STAGE_H (BL_OFF + 32 * B_STRIDE)
#define GEMM_SMEM (2 * STAGE_H * 2)

__global__ __launch_bounds__(256) void gemm_mma() {
    extern __shared__ __align__(16) __nv_bfloat16 sm[];
    const uint32_t sbase = smem_u32(sm);
    const int tid  = threadIdx.x;
    const int wid  = tid >> 5;
    const int lane = tid & 31;
    const int t  = blockIdx.z;
    const int m0 = blockIdx.x * BM;
    const int n0 = blockIdx.y * BN;
    const int wm = (wid & 3) * 32;
    const int wn = (wid >> 2) * 64;

    const __nv_bfloat16* Wh = g_wh + (size_t)t * L_ * H_;
    const __nv_bfloat16* Wl = g_wl + (size_t)t * L_ * H_;

    const int a_row0 = tid >> 2, a_kc = (tid & 3) * 8;
    const int b_kr0  = tid >> 4, b_nc = (tid & 15) * 8;

    auto prefetch = [&](int c) {
        const int k0 = c * BKC;
        const uint32_t st = sbase + (uint32_t)((c & 1) * STAGE_H) * 2;
        #pragma unroll
        for (int i = 0; i < 2; i++) {
            int row = a_row0 + i * 64;
            size_t g = (size_t)(m0 + row) * L_ + k0 + a_kc;
            uint32_t so = (uint32_t)(row * A_STRIDE + a_kc) * 2;
            cpa16(st + AH_OFF * 2 + so, g_xh + g);
            cpa16(st + AL_OFF * 2 + so, g_xl + g);
        }
        #pragma unroll
        for (int i = 0; i < 2; i++) {
            int kr = b_kr0 + i * 16;
            size_t g = (size_t)(k0 + kr) * H_ + n0 + b_nc;
            uint32_t so = (uint32_t)(kr * B_STRIDE + b_nc) * 2;
            cpa16(st + BH_OFF * 2 + so, Wh + g);
            cpa16(st + BL_OFF * 2 + so, Wl + g);
        }
    };

    float acc[2][8][4];
    #pragma unroll
    for (int mi = 0; mi < 2; mi++)
        #pragma unroll
        for (int ni = 0; ni < 8; ni++)
            #pragma unroll
            for (int j = 0; j < 4; j++) acc[mi][ni][j] = 0.0f;

    prefetch(0); CPA_COMMIT();

    const int a_lm_row = wm + (lane & 15);
    const int a_lm_col = (lane >> 4) * 8;
    const int b_lm_row = (lane < 16) ? lane : (lane - 16);
    const int b_lm_col = wn + ((lane >> 4) * 8);

    for (int c = 0; c < NCH; c++) {
        if (c + 1 < NCH) { prefetch(c + 1); CPA_COMMIT(); CPA_WAIT(1); }
        else             { CPA_WAIT(0); }
        __syncthreads();

        const uint32_t st = sbase + (uint32_t)((c & 1) * STAGE_H) * 2;
        #pragma unroll
        for (int ks = 0; ks < 2; ks++) {
            uint32_t a[2][4], b[4][4];
            // ---- pass 0: Ah x Bh ----
            #pragma unroll
            for (int mi = 0; mi < 2; mi++) {
                uint32_t ad = st + AH_OFF * 2 +
                    (uint32_t)((a_lm_row + mi * 16) * A_STRIDE + a_lm_col + ks * 16) * 2;
                LDSM4(a[mi][0], a[mi][1], a[mi][2], a[mi][3], ad);
            }
            #pragma unroll
            for (int nb = 0; nb < 4; nb++) {
                uint32_t bd = st + BH_OFF * 2 +
                    (uint32_t)((b_lm_row + ks * 16) * B_STRIDE + b_lm_col + nb * 16) * 2;
                LDSM4T(b[nb][0], b[nb][1], b[nb][2], b[nb][3], bd);
            }
            #pragma unroll
            for (int mi = 0; mi < 2; mi++)
                #pragma unroll
                for (int ni = 0; ni < 8; ni++)
                    MMA16816(acc[mi][ni], a[mi][0], a[mi][1], a[mi][2], a[mi][3],
                             b[ni >> 1][(ni & 1) * 2], b[ni >> 1][(ni & 1) * 2 + 1]);
            // ---- pass 1: Ah x Bl ----
            #pragma unroll
            for (int nb = 0; nb < 4; nb++) {
                uint32_t bd = st + BL_OFF * 2 +
                    (uint32_t)((b_lm_row + ks * 16) * B_STRIDE + b_lm_col + nb * 16) * 2;
                LDSM4T(b[nb][0], b[nb][1], b[nb][2], b[nb][3], bd);
            }
            #pragma unroll
            for (int mi = 0; mi < 2; mi++)
                #pragma unroll
                for (int ni = 0; ni < 8; ni++)
                    MMA16816(acc[mi][ni], a[mi][0], a[mi][1], a[mi][2], a[mi][3],
                             b[ni >> 1][(ni & 1) * 2], b[ni >> 1][(ni & 1) * 2 + 1]);
            // ---- pass 2: Al x Bh ----
            #pragma unroll
            for (int mi = 0; mi < 2; mi++) {
                uint32_t ad = st + AL_OFF * 2 +
                    (uint32_t)((a_lm_row + mi * 16) * A_STRIDE + a_lm_col + ks * 16) * 2;
                LDSM4(a[mi][0], a[mi][1], a[mi][2], a[mi][3], ad);
            }
            #pragma unroll
            for (int nb = 0; nb < 4; nb++) {
                uint32_t bd = st + BH_OFF * 2 +
                    (uint32_t)((b_lm_row + ks * 16) * B_STRIDE + b_lm_col + nb * 16) * 2;
                LDSM4T(b[nb][0], b[nb][1], b[nb][2], b[nb][3], bd);
            }
            #pragma unroll
            for (int mi = 0; mi < 2; mi++)
                #pragma unroll
                for (int ni = 0; ni < 8; ni++)
                    MMA16816(acc[mi][ni], a[mi][0], a[mi][1], a[mi][2], a[mi][3],
                             b[ni >> 1][(ni & 1) * 2], b[ni >> 1][(ni & 1) * 2 + 1]);
        }
        __syncthreads();
    }

    float* C = g_hidden + (size_t)t * B_ * H_;
    #pragma unroll
    for (int mi = 0; mi < 2; mi++) {
        int row = m0 + wm + mi * 16 + (lane >> 2);
        #pragma unroll
        for (int ni = 0; ni < 8; ni++) {
            int col = n0 + wn + ni * 8 + (lane & 3) * 2;
            *(float2*)(C + (size_t)row * H_ + col) =
                make_float2(acc[mi][ni][0], acc[mi][ni][1]);
            *(float2*)(C + (size_t)(row + 8) * H_ + col) =
                make_float2(acc[mi][ni][2], acc[mi][ni][3]);
        }
    }
}

// ---------------- top-64 via 2-pass radix select + small sort ---------------
__global__ __launch_bounds__(256) void topk_kernel() {
    __shared__ uint32_t hist[256];
    __shared__ uint32_t scn[256];
    __shared__ uint32_t cand[256];
    __shared__ uint32_t s_b1, s_c1, s_pfx, s_cnt;

    const int tid = threadIdx.x;
    const int b = blockIdx.x;
    const int t = blockIdx.y;
    const float* row = g_hidden + ((size_t)t * B_ + b) * H_;

    // load 8 elems/thread as order-preserving uint32
    uint32_t v[8];
    #pragma unroll
    for (int i = 0; i < 2; i++) {
        float4 f4 = ((const float4*)row)[tid + i * 256];
        float ff[4] = {f4.x, f4.y, f4.z, f4.w};
        #pragma unroll
        for (int j = 0; j < 4; j++) {
            uint32_t u = __float_as_uint(ff[j]);
            v[i * 4 + j] = (u & 0x80000000u) ? ~u : (u | 0x80000000u);
        }
    }

    // ---- pass 1: histogram on bits [24,32) ----
    hist[tid] = 0;
    __syncthreads();
    #pragma unroll
    for (int i = 0; i < 8; i++) atomicAdd(&hist[v[i] >> 24], 1u);
    __syncthreads();
    // suffix scan
    scn[tid] = hist[tid];
    __syncthreads();
    #pragma unroll
    for (int off = 1; off < 256; off <<= 1) {
        uint32_t add = (tid + off < 256) ? scn[tid + off] : 0u;
        __syncthreads();
        scn[tid] += add;
        __syncthreads();
    }
    {
        uint32_t above = (tid == 255) ? 0u : scn[tid + 1];
        if (scn[tid] >= K_ && above < K_) { s_b1 = (uint32_t)tid; s_c1 = above; }
    }
    __syncthreads();
    const uint32_t b1 = s_b1;
    const uint32_t need2 = K_ - s_c1;     // 1..64, from bucket b1

    // ---- pass 2: histogram on bits [16,24) within bucket b1 ----
    hist[tid] = 0;
    __syncthreads();
    #pragma unroll
    for (int i = 0; i < 8; i++)
        if ((v[i] >> 24) == b1) atomicAdd(&hist[(v[i] >> 16) & 0xFFu], 1u);
    __syncthreads();
    scn[tid] = hist[tid];
    __syncthreads();
    #pragma unroll
    for (int off = 1; off < 256; off <<= 1) {
        uint32_t add = (tid + off < 256) ? scn[tid + off] : 0u;
        __syncthreads();
        scn[tid] += add;
        __syncthreads();
    }
    {
        uint32_t above = (tid == 255) ? 0u : scn[tid + 1];
        if (scn[tid] >= need2 && above < need2)
            s_pfx = (b1 << 8) | (uint32_t)tid;
    }
    if (tid == 0) s_cnt = 0;
    cand[tid] = 0;
    __syncthreads();
    const uint32_t pfx = s_pfx;

    // ---- collect candidates with 16-bit prefix >= pfx (count in [64,~72]) --
    #pragma unroll
    for (int i = 0; i < 8; i++) {
        if ((v[i] >> 16) >= pfx) {
            uint32_t p = atomicAdd(&s_cnt, 1u);
            if (p < 256) cand[p] = v[i];
        }
    }
    __syncthreads();

    // ---- bitonic sort 256 descending ----
    for (int k = 2; k <= 256; k <<= 1) {
        for (int j = k >> 1; j > 0; j >>= 1) {
            int ixj = tid ^ j;
            if (ixj > tid) {
                uint32_t a = cand[tid], c = cand[ixj];
                bool desc = ((tid & k) == 0);
                if (desc ? (a < c) : (a > c)) { cand[tid] = c; cand[ixj] = a; }
            }
            __syncthreads();
        }
    }

    if (tid < K_) {
        uint32_t u = cand[tid];
        uint32_t orig = (u & 0x80000000u) ? (u & 0x7FFFFFFFu) : ~u;
        g_sparse[((size_t)t * B_ + b) * K_ + tid] = __uint_as_float(orig);
    }
}

// ---------------- dense + GELU + LayerNorm (16 rows per block) ---------------
#define DB 16   // b-rows per block

__global__ __launch_bounds__(256) void dense_kernel(const float* __restrict__ dW,
                                                    const float* __restrict__ db,
                                                    const float* __restrict__ gamma,
                                                    const float* __restrict__ beta,
                                                    float* __restrict__ out) {
    __shared__ float gs[DB][K_];          // 4 KB
    __shared__ float wred[DB][8];
    __shared__ float s_mean[DB], s_rstd[DB];

    const int bg = blockIdx.x * DB;
    const int t  = blockIdx.y;
    const int o  = threadIdx.x;
    const int wid = o >> 5, lane = o & 31;

    // load 16 sparse rows (coalesced)
    #pragma unroll
    for (int i = 0; i < DB * K_ / 256; i++) {
        int lin = o + i * 256;
        gs[lin >> 6][lin & 63] =
            g_sparse[((size_t)t * B_ + bg) * K_ + lin];
    }
    __syncthreads();

    const float* W = dW + (size_t)t * K_ * O_;
    float acc[DB];
    const float bias = db[t * O_ + o];
    #pragma unroll
    for (int j = 0; j < DB; j++) acc[j] = bias;

    #pragma unroll 8
    for (int k = 0; k < K_; k++) {
        float w = W[k * O_ + o];
        #pragma unroll
        for (int j = 0; j < DB; j++) acc[j] = fmaf(gs[j][k], w, acc[j]);
    }

    float y[DB];
    #pragma unroll
    for (int j = 0; j < DB; j++)
        y[j] = 0.5f * acc[j] * (1.0f + erff(acc[j] * 0.70710678118654752f));

    // mean
    #pragma unroll
    for (int j = 0; j < DB; j++) {
        float v = y[j];
        #pragma unroll
        for (int off = 16; off; off >>= 1) v += __shfl_xor_sync(0xffffffffu, v, off);
        if (lane == 0) wred[j][wid] = v;
    }
    __syncthreads();
    if (o < DB) {
        float s = 0.f;
        #pragma unroll
        for (int w = 0; w < 8; w++) s += wred[o][w];
        s_mean[o] = s * (1.0f / O_);
    }
    __syncthreads();
    // variance
    #pragma unroll
    for (int j = 0; j < DB; j++) {
        float d = y[j] - s_mean[j];
        float v = d * d;
        #pragma unroll
        for (int off = 16; off; off >>= 1) v += __shfl_xor_sync(0xffffffffu, v, off);
        if (lane == 0) wred[j][wid] = v;
    }
    __syncthreads();
    if (o < DB) {
        float s = 0.f;
        #pragma unroll
        for (int w = 0; w < 8; w++) s += wred[o][w];
        s_rstd[o] = rsqrtf(s * (1.0f / O_) + 1e-6f);
    }
    __syncthreads();

    const float gm = gamma[t * O_ + o];
    const float bt = beta[t * O_ + o];
    #pragma unroll
    for (int j = 0; j < DB; j++) {
        out[((size_t)(bg + j) * T_ + t) * O_ + o] =
            (y[j] - s_mean[j]) * s_rstd[j] * gm + bt;
    }
}

// ---------------------------------------------------------------------------
extern "C" void kernel_launch(void* const* d_in, const int* in_sizes, int n_in,
                              void* d_out, int out_size) {
    const float* x     = (const float*)d_in[0];
    const float* Wt    = (const float*)d_in[1];
    const float* dW    = (const float*)d_in[2];
    const float* db    = (const float*)d_in[3];
    const float* gamma = (const float*)d_in[4];
    const float* beta  = (const float*)d_in[5];
    float* out = (float*)d_out;

    __nv_bfloat16 *xh, *xl, *wh, *wl;
    cudaGetSymbolAddress((void**)&xh, g_xh);
    cudaGetSymbolAddress((void**)&xl, g_xl);
    cudaGetSymbolAddress((void**)&wh, g_wh);
    cudaGetSymbolAddress((void**)&wl, g_wl);

    cudaFuncSetAttribute(gemm_mma, cudaFuncAttributeMaxDynamicSharedMemorySize,
                         GEMM_SMEM);

    conv_split<<<(B_ * L_ / 4) / 256, 256>>>(x, xh, xl);
    conv_split<<<((size_t)T_ * L_ * H_ / 4) / 256, 256>>>(Wt, wh, wl);
    gemm_mma<<<dim3(B_ / BM, H_ / BN, T_), 256, GEMM_SMEM>>>();
    topk_kernel<<<dim3(B_, T_), 256>>>();
    dense_kernel<<<dim3(B_ / DB, T_), 256>>>(dW, db, gamma, beta, out);
}

// round 10
// speedup vs baseline: 3.8345x; 1.0969x over previous
#include <cuda_runtime.h>
#include <cuda_bf16.h>
#include <math.h>
#include <stdint.h>

#define B_ 1024
#define L_ 1024
#define T_ 32
#define H_ 2048
#define K_ 64
#define O_ 256

// ---------------- static device scratch (allocation-guard safe) ------------
__device__ float g_hidden[(size_t)T_ * B_ * H_];          // 256 MB [t][b][h]
__device__ float g_sparse[(size_t)T_ * B_ * K_];          // 8 MB
__device__ __nv_bfloat16 g_xh[(size_t)B_ * L_];           // [b][l] hi
__device__ __nv_bfloat16 g_xl[(size_t)B_ * L_];           // [b][l] lo
__device__ __nv_bfloat16 g_wh[(size_t)T_ * L_ * H_];      // [t][l][h] hi (k-major)
__device__ __nv_bfloat16 g_wl[(size_t)T_ * L_ * H_];      // [t][l][h] lo

// ---------------- helpers ---------------------------------------------------
__device__ __forceinline__ uint32_t smem_u32(const void* p) {
    uint32_t a;
    asm("{ .reg .u64 t; cvta.to.shared.u64 t, %1; cvt.u32.u64 %0, t; }"
        : "=r"(a) : "l"(p));
    return a;
}
__device__ __forceinline__ void cpa16(uint32_t s, const void* g) {
    asm volatile("cp.async.cg.shared.global [%0], [%1], 16;" :: "r"(s), "l"(g));
}
#define CPA_COMMIT() asm volatile("cp.async.commit_group;" ::: "memory")
#define CPA_WAIT(n)  asm volatile("cp.async.wait_group %0;" :: "n"(n) : "memory")

#define LDSM4(r0, r1, r2, r3, a)                                               \
    asm volatile("ldmatrix.sync.aligned.m8n8.x4.shared.b16 {%0,%1,%2,%3},[%4];"\
                 : "=r"(r0), "=r"(r1), "=r"(r2), "=r"(r3) : "r"(a))
#define LDSM4T(r0, r1, r2, r3, a)                                              \
    asm volatile("ldmatrix.sync.aligned.m8n8.x4.trans.shared.b16 "             \
                 "{%0,%1,%2,%3},[%4];"                                         \
                 : "=r"(r0), "=r"(r1), "=r"(r2), "=r"(r3) : "r"(a))
#define MMA16816(c, a0, a1, a2, a3, b0, b1)                                    \
    asm volatile("mma.sync.aligned.m16n8k16.row.col.f32.bf16.bf16.f32 "        \
                 "{%0,%1,%2,%3},{%4,%5,%6,%7},{%8,%9},{%0,%1,%2,%3};"          \
                 : "+f"((c)[0]), "+f"((c)[1]), "+f"((c)[2]), "+f"((c)[3])      \
                 : "r"(a0), "r"(a1), "r"(a2), "r"(a3), "r"(b0), "r"(b1))

// ---------------- conversion: f32 -> (hi, lo) bf16 --------------------------
__global__ __launch_bounds__(256) void conv_split(const float* __restrict__ src,
                                                  __nv_bfloat16* __restrict__ dh,
                                                  __nv_bfloat16* __restrict__ dl) {
    size_t i = (size_t)blockIdx.x * 256 + threadIdx.x;   // float4 index
    float4 v = ((const float4*)src)[i];
    float vv[4] = {v.x, v.y, v.z, v.w};
    __nv_bfloat16 hi[4], lo[4];
    #pragma unroll
    for (int j = 0; j < 4; j++) {
        hi[j] = __float2bfloat16(vv[j]);
        lo[j] = __float2bfloat16(vv[j] - __bfloat162float(hi[j]));
    }
    ((uint2*)dh)[i] = *(uint2*)hi;
    ((uint2*)dl)[i] = *(uint2*)lo;
}

// ---------------- HMMA GEMM: hidden[t] = x @ Wt[t] --------------------------
#define BM 128
#define BN 128
#define BKC 32
#define NCH (L_ / BKC)          // 32 chunks

#define A_STRIDE 40
#define B_STRIDE 136
#define AH_OFF 0
#define AL_OFF (128 * A_STRIDE)
#define BH_OFF (2 * 128 * A_STRIDE)
#define BL_OFF (BH_OFF + 32 * B_STRIDE)
#define STAGE_H (BL_OFF + 32 * B_STRIDE)
#define GEMM_SMEM (2 * STAGE_H * 2)

__global__ __launch_bounds__(256) void gemm_mma() {
    extern __shared__ __align__(16) __nv_bfloat16 sm[];
    const uint32_t sbase = smem_u32(sm);
    const int tid  = threadIdx.x;
    const int wid  = tid >> 5;
    const int lane = tid & 31;
    const int t  = blockIdx.z;
    const int m0 = blockIdx.x * BM;
    const int n0 = blockIdx.y * BN;
    const int wm = (wid & 3) * 32;
    const int wn = (wid >> 2) * 64;

    const __nv_bfloat16* Wh = g_wh + (size_t)t * L_ * H_;
    const __nv_bfloat16* Wl = g_wl + (size_t)t * L_ * H_;

    const int a_row0 = tid >> 2, a_kc = (tid & 3) * 8;
    const int b_kr0  = tid >> 4, b_nc = (tid & 15) * 8;

    auto prefetch = [&](int c) {
        const int k0 = c * BKC;
        const uint32_t st = sbase + (uint32_t)((c & 1) * STAGE_H) * 2;
        #pragma unroll
        for (int i = 0; i < 2; i++) {
            int row = a_row0 + i * 64;
            size_t g = (size_t)(m0 + row) * L_ + k0 + a_kc;
            uint32_t so = (uint32_t)(row * A_STRIDE + a_kc) * 2;
            cpa16(st + AH_OFF * 2 + so, g_xh + g);
            cpa16(st + AL_OFF * 2 + so, g_xl + g);
        }
        #pragma unroll
        for (int i = 0; i < 2; i++) {
            int kr = b_kr0 + i * 16;
            size_t g = (size_t)(k0 + kr) * H_ + n0 + b_nc;
            uint32_t so = (uint32_t)(kr * B_STRIDE + b_nc) * 2;
            cpa16(st + BH_OFF * 2 + so, Wh + g);
            cpa16(st + BL_OFF * 2 + so, Wl + g);
        }
    };

    float acc[2][8][4];
    #pragma unroll
    for (int mi = 0; mi < 2; mi++)
        #pragma unroll
        for (int ni = 0; ni < 8; ni++)
            #pragma unroll
            for (int j = 0; j < 4; j++) acc[mi][ni][j] = 0.0f;

    prefetch(0); CPA_COMMIT();

    const int a_lm_row = wm + (lane & 15);
    const int a_lm_col = (lane >> 4) * 8;
    const int b_lm_row = (lane < 16) ? lane : (lane - 16);
    const int b_lm_col = wn + ((lane >> 4) * 8);

    for (int c = 0; c < NCH; c++) {
        if (c + 1 < NCH) { prefetch(c + 1); CPA_COMMIT(); CPA_WAIT(1); }
        else             { CPA_WAIT(0); }
        __syncthreads();

        const uint32_t st = sbase + (uint32_t)((c & 1) * STAGE_H) * 2;
        #pragma unroll
        for (int ks = 0; ks < 2; ks++) {
            uint32_t a[2][4], bh[4][4], bl[4][4];
            // load Ah, Bh, Bl fragments once
            #pragma unroll
            for (int mi = 0; mi < 2; mi++) {
                uint32_t ad = st + AH_OFF * 2 +
                    (uint32_t)((a_lm_row + mi * 16) * A_STRIDE + a_lm_col + ks * 16) * 2;
                LDSM4(a[mi][0], a[mi][1], a[mi][2], a[mi][3], ad);
            }
            #pragma unroll
            for (int nb = 0; nb < 4; nb++) {
                uint32_t bd = st + BH_OFF * 2 +
                    (uint32_t)((b_lm_row + ks * 16) * B_STRIDE + b_lm_col + nb * 16) * 2;
                LDSM4T(bh[nb][0], bh[nb][1], bh[nb][2], bh[nb][3], bd);
            }
            #pragma unroll
            for (int nb = 0; nb < 4; nb++) {
                uint32_t bd = st + BL_OFF * 2 +
                    (uint32_t)((b_lm_row + ks * 16) * B_STRIDE + b_lm_col + nb * 16) * 2;
                LDSM4T(bl[nb][0], bl[nb][1], bl[nb][2], bl[nb][3], bd);
            }
            // pass 0: Ah x Bh
            #pragma unroll
            for (int mi = 0; mi < 2; mi++)
                #pragma unroll
                for (int ni = 0; ni < 8; ni++)
                    MMA16816(acc[mi][ni], a[mi][0], a[mi][1], a[mi][2], a[mi][3],
                             bh[ni >> 1][(ni & 1) * 2], bh[ni >> 1][(ni & 1) * 2 + 1]);
            // pass 1: Ah x Bl (Ah held)
            #pragma unroll
            for (int mi = 0; mi < 2; mi++)
                #pragma unroll
                for (int ni = 0; ni < 8; ni++)
                    MMA16816(acc[mi][ni], a[mi][0], a[mi][1], a[mi][2], a[mi][3],
                             bl[ni >> 1][(ni & 1) * 2], bl[ni >> 1][(ni & 1) * 2 + 1]);
            // pass 2: Al x Bh (Bh held; reload A regs with Al)
            #pragma unroll
            for (int mi = 0; mi < 2; mi++) {
                uint32_t ad = st + AL_OFF * 2 +
                    (uint32_t)((a_lm_row + mi * 16) * A_STRIDE + a_lm_col + ks * 16) * 2;
                LDSM4(a[mi][0], a[mi][1], a[mi][2], a[mi][3], ad);
            }
            #pragma unroll
            for (int mi = 0; mi < 2; mi++)
                #pragma unroll
                for (int ni = 0; ni < 8; ni++)
                    MMA16816(acc[mi][ni], a[mi][0], a[mi][1], a[mi][2], a[mi][3],
                             bh[ni >> 1][(ni & 1) * 2], bh[ni >> 1][(ni & 1) * 2 + 1]);
        }
        __syncthreads();
    }

    float* C = g_hidden + (size_t)t * B_ * H_;
    #pragma unroll
    for (int mi = 0; mi < 2; mi++) {
        int row = m0 + wm + mi * 16 + (lane >> 2);
        #pragma unroll
        for (int ni = 0; ni < 8; ni++) {
            int col = n0 + wn + ni * 8 + (lane & 3) * 2;
            *(float2*)(C + (size_t)row * H_ + col) =
                make_float2(acc[mi][ni][0], acc[mi][ni][1]);
            *(float2*)(C + (size_t)(row + 8) * H_ + col) =
                make_float2(acc[mi][ni][2], acc[mi][ni][3]);
        }
    }
}

// ---------------- top-64 via 2-pass radix select + rank selection -----------
__global__ __launch_bounds__(256) void topk_kernel() {
    __shared__ uint32_t hist[256];
    __shared__ uint32_t wtot[8];
    __shared__ uint32_t cand_v[256];
    __shared__ uint32_t cand_i[256];
    __shared__ uint32_t s_b1, s_c1, s_pfx, s_cnt;

    const int tid = threadIdx.x;
    const int lane = tid & 31;
    const int wrp  = tid >> 5;
    const int b = blockIdx.x;
    const int t = blockIdx.y;
    const float* row = g_hidden + ((size_t)t * B_ + b) * H_;

    // load 8 elems/thread as order-preserving uint32
    uint32_t v[8];
    #pragma unroll
    for (int i = 0; i < 2; i++) {
        float4 f4 = ((const float4*)row)[tid + i * 256];
        float ff[4] = {f4.x, f4.y, f4.z, f4.w};
        #pragma unroll
        for (int j = 0; j < 4; j++) {
            uint32_t u = __float_as_uint(ff[j]);
            v[i * 4 + j] = (u & 0x80000000u) ? ~u : (u | 0x80000000u);
        }
    }

    // ---- pass 1: histogram on bits [24,32) ----
    hist[tid] = 0;
    __syncthreads();
    #pragma unroll
    for (int i = 0; i < 8; i++) atomicAdd(&hist[v[i] >> 24], 1u);
    __syncthreads();
    // warp suffix scan (bin tid covered by warp wrp, lane)
    {
        uint32_t h = hist[tid];
        uint32_t s = h;
        #pragma unroll
        for (int off = 1; off < 32; off <<= 1) {
            uint32_t tmp = __shfl_down_sync(0xffffffffu, s, off);
            if (lane + off < 32) s += tmp;
        }
        if (lane == 0) wtot[wrp] = s;
        __syncthreads();
        uint32_t later = 0;
        for (int w = wrp + 1; w < 8; w++) later += wtot[w];
        uint32_t scn = s + later;        // count of elems in buckets >= tid
        uint32_t above = scn - h;        // strictly greater buckets
        if (scn >= K_ && above < K_) { s_b1 = (uint32_t)tid; s_c1 = above; }
    }
    __syncthreads();
    const uint32_t b1 = s_b1;
    const uint32_t need2 = K_ - s_c1;    // 1..64

    // ---- pass 2: histogram on bits [16,24) within bucket b1 ----
    hist[tid] = 0;
    __syncthreads();
    #pragma unroll
    for (int i = 0; i < 8; i++)
        if ((v[i] >> 24) == b1) atomicAdd(&hist[(v[i] >> 16) & 0xFFu], 1u);
    __syncthreads();
    {
        uint32_t h = hist[tid];
        uint32_t s = h;
        #pragma unroll
        for (int off = 1; off < 32; off <<= 1) {
            uint32_t tmp = __shfl_down_sync(0xffffffffu, s, off);
            if (lane + off < 32) s += tmp;
        }
        if (lane == 0) wtot[wrp] = s;
        if (tid == 0) s_cnt = 0;
        __syncthreads();
        uint32_t later = 0;
        for (int w = wrp + 1; w < 8; w++) later += wtot[w];
        uint32_t scn = s + later;
        uint32_t above = scn - h;
        if (scn >= need2 && above < need2)
            s_pfx = (b1 << 8) | (uint32_t)tid;
    }
    __syncthreads();
    const uint32_t pfx = s_pfx;

    // ---- collect candidates (16-bit prefix >= pfx), value + index ----------
    #pragma unroll
    for (int i = 0; i < 8; i++) {
        if ((v[i] >> 16) >= pfx) {
            uint32_t p = atomicAdd(&s_cnt, 1u);
            if (p < 256) {
                cand_v[p] = v[i];
                cand_i[p] = (uint32_t)((tid + (i >> 2) * 256) * 4 + (i & 3));
            }
        }
    }
    __syncthreads();

    // ---- rank selection (no sort): rank = #greater (+ index tie-break) ----
    const int cnt = (int)min(s_cnt, 256u);
    if (tid < cnt) {
        const uint32_t mv = cand_v[tid];
        const uint32_t mi = cand_i[tid];
        int r = 0;
        for (int k = 0; k < cnt; k++) {
            uint32_t cv = cand_v[k];
            r += (cv > mv) || (cv == mv && cand_i[k] < mi);
        }
        if (r < K_) {
            uint32_t orig = (mv & 0x80000000u) ? (mv & 0x7FFFFFFFu) : ~mv;
            g_sparse[((size_t)t * B_ + b) * K_ + r] = __uint_as_float(orig);
        }
    }
}

// ---------------- dense + GELU + LayerNorm (16 rows per block) ---------------
#define DB 16   // b-rows per block

__global__ __launch_bounds__(256) void dense_kernel(const float* __restrict__ dW,
                                                    const float* __restrict__ db,
                                                    const float* __restrict__ gamma,
                                                    const float* __restrict__ beta,
                                                    float* __restrict__ out) {
    __shared__ float gs[DB][K_];          // 4 KB
    __shared__ float wred[DB][8];
    __shared__ float s_mean[DB], s_rstd[DB];

    const int bg = blockIdx.x * DB;
    const int t  = blockIdx.y;
    const int o  = threadIdx.x;
    const int wid = o >> 5, lane = o & 31;

    #pragma unroll
    for (int i = 0; i < DB * K_ / 256; i++) {
        int lin = o + i * 256;
        gs[lin >> 6][lin & 63] =
            g_sparse[((size_t)t * B_ + bg) * K_ + lin];
    }
    __syncthreads();

    const float* W = dW + (size_t)t * K_ * O_;
    float acc[DB];
    const float bias = db[t * O_ + o];
    #pragma unroll
    for (int j = 0; j < DB; j++) acc[j] = bias;

    #pragma unroll 8
    for (int k = 0; k < K_; k++) {
        float w = W[k * O_ + o];
        #pragma unroll
        for (int j = 0; j < DB; j++) acc[j] = fmaf(gs[j][k], w, acc[j]);
    }

    float y[DB];
    #pragma unroll
    for (int j = 0; j < DB; j++)
        y[j] = 0.5f * acc[j] * (1.0f + erff(acc[j] * 0.70710678118654752f));

    #pragma unroll
    for (int j = 0; j < DB; j++) {
        float v = y[j];
        #pragma unroll
        for (int off = 16; off; off >>= 1) v += __shfl_xor_sync(0xffffffffu, v, off);
        if (lane == 0) wred[j][wid] = v;
    }
    __syncthreads();
    if (o < DB) {
        float s = 0.f;
        #pragma unroll
        for (int w = 0; w < 8; w++) s += wred[o][w];
        s_mean[o] = s * (1.0f / O_);
    }
    __syncthreads();
    #pragma unroll
    for (int j = 0; j < DB; j++) {
        float d = y[j] - s_mean[j];
        float v = d * d;
        #pragma unroll
        for (int off = 16; off; off >>= 1) v += __shfl_xor_sync(0xffffffffu, v, off);
        if (lane == 0) wred[j][wid] = v;
    }
    __syncthreads();
    if (o < DB) {
        float s = 0.f;
        #pragma unroll
        for (int w = 0; w < 8; w++) s += wred[o][w];
        s_rstd[o] = rsqrtf(s * (1.0f / O_) + 1e-6f);
    }
    __syncthreads();

    const float gm = gamma[t * O_ + o];
    const float bt = beta[t * O_ + o];
    #pragma unroll
    for (int j = 0; j < DB; j++) {
        out[((size_t)(bg + j) * T_ + t) * O_ + o] =
            (y[j] - s_mean[j]) * s_rstd[j] * gm + bt;
    }
}

// ---------------------------------------------------------------------------
extern "C" void kernel_launch(void* const* d_in, const int* in_sizes, int n_in,
                              void* d_out, int out_size) {
    const float* x     = (const float*)d_in[0];
    const float* Wt    = (const float*)d_in[1];
    const float* dW    = (const float*)d_in[2];
    const float* db    = (const float*)d_in[3];
    const float* gamma = (const float*)d_in[4];
    const float* beta  = (const float*)d_in[5];
    float* out = (float*)d_out;

    __nv_bfloat16 *xh, *xl, *wh, *wl;
    cudaGetSymbolAddress((void**)&xh, g_xh);
    cudaGetSymbolAddress((void**)&xl, g_xl);
    cudaGetSymbolAddress((void**)&wh, g_wh);
    cudaGetSymbolAddress((void**)&wl, g_wl);

    cudaFuncSetAttribute(gemm_mma, cudaFuncAttributeMaxDynamicSharedMemorySize,
                         GEMM_SMEM);

    conv_split<<<(B_ * L_ / 4) / 256, 256>>>(x, xh, xl);
    conv_split<<<((size_t)T_ * L_ * H_ / 4) / 256, 256>>>(Wt, wh, wl);
    gemm_mma<<<dim3(B_ / BM, H_ / BN, T_), 256, GEMM_SMEM>>>();
    topk_kernel<<<dim3(B_, T_), 256>>>();
    dense_kernel<<<dim3(B_ / DB, T_), 256>>>(dW, db, gamma, beta, out);
}